// round 9
// baseline (speedup 1.0000x reference)
#include <cuda_runtime.h>

#define NMAX 50000
#define EMAX 800000
#define DD 64
#define NPB 128           // dst nodes per block
#define AP 64             // sA pitch (row-major [node][k])
#define SCAN_CHUNK 1024
#define MAXB ((NMAX + SCAN_CHUNK - 1) / SCAN_CHUNK)   // 49

// -------- device scratch (no allocations allowed) --------
__device__ int   g_is64;
__device__ int   g_src[EMAX];
__device__ int   g_dst[EMAX];
__device__ int   g_deg[NMAX];
__device__ int   g_rowptr[NMAX + 2];
__device__ int   g_cursor[NMAX];
__device__ int   g_col[EMAX];
__device__ int   g_bsum[MAXB + 1];
__device__ float g_h1[(size_t)NMAX * DD];

// ---- packed f32x2 helpers (sm_103a; ptxas never auto-emits FFMA2) ----
__device__ __forceinline__ unsigned long long bcast2(float a) {
    unsigned long long r;
    asm("mov.b64 %0, {%1, %1};" : "=l"(r) : "f"(a));
    return r;
}
__device__ __forceinline__ unsigned long long pack2(float lo, float hi) {
    unsigned long long r;
    asm("mov.b64 %0, {%1, %2};" : "=l"(r) : "f"(lo), "f"(hi));
    return r;
}
__device__ __forceinline__ void fma2(unsigned long long& acc,
                                     unsigned long long a, unsigned long long b) {
    asm("fma.rn.f32x2 %0, %1, %2, %0;" : "+l"(acc) : "l"(a), "l"(b));
}
__device__ __forceinline__ void unpack2(unsigned long long p, float& lo, float& hi) {
    asm("mov.b64 {%0, %1}, %2;" : "=f"(lo), "=f"(hi) : "l"(p));
}

// ============ init deg + edge dtype detection (fused) ============
__global__ void detect_init_kernel(const void* __restrict__ edge, int n) {
    int i = blockIdx.x * blockDim.x + threadIdx.x;
    if (i < n) g_deg[i] = 0;
    if (i == 0) {
        const long long* p = (const long long*)edge;
        int ok = 1;
        for (int k = 0; k < 64; k++) {
            long long v = p[k];
            if (v < 0 || v >= n) { ok = 0; break; }
        }
        g_is64 = ok;
    }
}

// Materialize clamped int32 src/dst AND count degrees in one pass.
__global__ void convert_count_kernel(const void* __restrict__ edge, int e, int n) {
    int i = blockIdx.x * blockDim.x + threadIdx.x;
    if (i >= e) return;
    int s, d;
    if (g_is64) {
        const long long* p = (const long long*)edge;
        s = (int)p[i];
        d = (int)p[e + i];
    } else {
        const int* p = (const int*)edge;
        s = p[i];
        d = p[e + i];
    }
    s = min(max(s, 0), n - 1);
    d = min(max(d, 0), n - 1);
    g_src[i] = s;
    g_dst[i] = d;
    atomicAdd(&g_deg[d], 1);
}

// ============ coalesced scan: bsum -> scan (block offsets inlined) ============
__global__ void bsum_kernel(int n) {
    __shared__ int ws[32];
    int b = blockIdx.x, t = threadIdx.x;
    int lane = t & 31, wid = t >> 5;
    int i = b * SCAN_CHUNK + t;
    int v = (i < n) ? g_deg[i] : 0;
    #pragma unroll
    for (int o = 16; o > 0; o >>= 1) v += __shfl_xor_sync(0xffffffffu, v, o);
    if (lane == 0) ws[wid] = v;
    __syncthreads();
    if (t < 32) {
        int s = ws[t];
        #pragma unroll
        for (int o = 16; o > 0; o >>= 1) s += __shfl_xor_sync(0xffffffffu, s, o);
        if (t == 0) g_bsum[b] = s;
    }
}

// per-chunk exclusive scan; block offset computed in-kernel from g_bsum
__global__ void scan_kernel(int n, int e) {
    __shared__ int ws[32];
    __shared__ int sOff;
    int b = blockIdx.x, t = threadIdx.x;
    int lane = t & 31, wid = t >> 5;

    if (wid == 0) {
        int off = 0;
        for (int j = lane; j < b; j += 32) off += g_bsum[j];
        #pragma unroll
        for (int o = 16; o > 0; o >>= 1) off += __shfl_xor_sync(0xffffffffu, off, o);
        if (lane == 0) sOff = off;
    }

    int i = b * SCAN_CHUNK + t;
    int v = (i < n) ? g_deg[i] : 0;
    int x = v;
    #pragma unroll
    for (int o = 1; o < 32; o <<= 1) {
        int y = __shfl_up_sync(0xffffffffu, x, o);
        if (lane >= o) x += y;
    }
    if (lane == 31) ws[wid] = x;
    __syncthreads();
    if (wid == 0) {
        int w = ws[lane];
        #pragma unroll
        for (int o = 1; o < 32; o <<= 1) {
            int y = __shfl_up_sync(0xffffffffu, w, o);
            if (lane >= o) w += y;
        }
        ws[lane] = w;
    }
    __syncthreads();
    int incl = x + (wid > 0 ? ws[wid - 1] : 0);
    int excl = incl - v + sOff;
    if (i < n) { g_rowptr[i] = excl; g_cursor[i] = excl; }
    if (b == 0 && t == 0) g_rowptr[n] = e;
}

__global__ void fill_kernel(int e) {
    int i = blockIdx.x * blockDim.x + threadIdx.x;
    if (i < e) {
        int p = atomicAdd(&g_cursor[g_dst[i]], 1);
        g_col[p] = g_src[i];
    }
}

// ================= fused layer =================
// mode 0: in = x param, out = g_h1, epilogue leaky_relu(0.01)
// mode 1: in = g_h1,    out = out param, epilogue row-L2-normalize
__global__ __launch_bounds__(256) void layer_kernel(
    const float* __restrict__ in_p,
    const float* __restrict__ Wl,      // [64,64] row-major
    const float* __restrict__ bias,    // [64]
    const float* __restrict__ Wr,      // [64,64] row-major
    float* __restrict__ out_p,
    int n, int mode)
{
    __shared__ float sA[NPB * AP];     // [128 nodes][64 k]  32KB
    __shared__ float sW[64 * 64];      // [64 k][64 j] (transposed weight) 16KB

    const float* __restrict__ in = (mode == 0) ? in_p : g_h1;
    float* __restrict__ out      = (mode == 0) ? g_h1 : out_p;

    int t = threadIdx.x;
    int wid = t >> 5, lane = t & 31;
    int half = lane >> 4;        // 0/1: which edge of the pair
    int c4 = (lane & 15) * 4;    // float4 column group
    int node0 = blockIdx.x * NPB;

    // load Wl^T
    for (int idx = t; idx < 64 * 64; idx += 256) {
        int j = idx >> 6, k = idx & 63;
        sW[k * 64 + j] = Wl[idx];
    }

    // ---- prefetch rowptr: 32 lanes cover beg/end of this warp's 16 nodes ----
    int pidx = node0 + wid + ((lane >> 1) * 8) + (lane & 1);
    pidx = min(pidx, n);
    int rp = g_rowptr[pidx];

    // ---- phase 1: mean aggregation -> sA (16 nodes per warp) ----
    #pragma unroll
    for (int it = 0; it < 16; it++) {
        int ni = wid + it * 8;
        int node = node0 + ni;
        float4 a0 = {0.f, 0.f, 0.f, 0.f}, a1 = {0.f, 0.f, 0.f, 0.f};
        int beg = __shfl_sync(0xffffffffu, rp, it * 2);
        int end = __shfl_sync(0xffffffffu, rp, it * 2 + 1);
        if (node < n) {
            int e0 = beg;
            for (; e0 + 4 <= end; e0 += 4) {
                int sa = g_col[e0 + half];
                int sb = g_col[e0 + 2 + half];
                float4 v0 = *(const float4*)&in[(size_t)sa * 64 + c4];
                float4 v1 = *(const float4*)&in[(size_t)sb * 64 + c4];
                a0.x += v0.x; a0.y += v0.y; a0.z += v0.z; a0.w += v0.w;
                a1.x += v1.x; a1.y += v1.y; a1.z += v1.z; a1.w += v1.w;
            }
            if (e0 + 2 <= end) {
                int sa = g_col[e0 + half];
                float4 v0 = *(const float4*)&in[(size_t)sa * 64 + c4];
                a0.x += v0.x; a0.y += v0.y; a0.z += v0.z; a0.w += v0.w;
                e0 += 2;
            }
            if (e0 < end && half == 0) {
                int sa = g_col[e0];
                float4 v0 = *(const float4*)&in[(size_t)sa * 64 + c4];
                a1.x += v0.x; a1.y += v0.y; a1.z += v0.z; a1.w += v0.w;
            }
            a0.x += a1.x; a0.y += a1.y; a0.z += a1.z; a0.w += a1.w;
            a0.x += __shfl_xor_sync(0xffffffffu, a0.x, 16);
            a0.y += __shfl_xor_sync(0xffffffffu, a0.y, 16);
            a0.z += __shfl_xor_sync(0xffffffffu, a0.z, 16);
            a0.w += __shfl_xor_sync(0xffffffffu, a0.w, 16);
            int deg = end - beg;
            float inv = 1.0f / (float)(deg > 0 ? deg : 1);
            a0.x *= inv; a0.y *= inv; a0.z *= inv; a0.w *= inv;
        }
        if (half == 0)
            *(float4*)&sA[ni * AP + c4] = a0;
    }
    __syncthreads();

    // ---- GEMM: 8x4 register tile, packed f32x2 accumulators, bias-init ----
    int rg = t >> 4, cg = t & 15;
    int i0 = rg * 8, j0 = cg * 4;
    float4 bv = *(const float4*)&bias[j0];
    unsigned long long bx = pack2(bv.x, bv.y), by = pack2(bv.z, bv.w);
    unsigned long long accp[8][2];
    #pragma unroll
    for (int r = 0; r < 8; r++) { accp[r][0] = bx; accp[r][1] = by; }

    // pass 1: acc += mean @ Wl^T
    #pragma unroll 2
    for (int k = 0; k < 64; k += 4) {
        float4 a[8];
        #pragma unroll
        for (int r = 0; r < 8; r++)
            a[r] = *(const float4*)&sA[(i0 + r) * AP + k];
        #pragma unroll
        for (int kk = 0; kk < 4; kk++) {
            ulonglong2 wp = *(const ulonglong2*)&sW[(k + kk) * 64 + j0];
            #pragma unroll
            for (int r = 0; r < 8; r++) {
                float s = (kk == 0) ? a[r].x : (kk == 1) ? a[r].y
                        : (kk == 2) ? a[r].z : a[r].w;
                unsigned long long p = bcast2(s);
                fma2(accp[r][0], p, wp.x);
                fma2(accp[r][1], p, wp.y);
            }
        }
    }
    __syncthreads();

    // ---- swap operands: sA <- x (from global, coalesced), sW <- Wr^T ----
    for (int i = t; i < NPB * 16; i += 256) {     // 16 float4 per row
        int nd = i >> 4;
        int col4 = (i & 15) * 4;
        float4 v = {0.f, 0.f, 0.f, 0.f};
        if (node0 + nd < n)
            v = *(const float4*)&in[(size_t)(node0 + nd) * 64 + col4];
        *(float4*)&sA[nd * AP + col4] = v;
    }
    for (int idx = t; idx < 64 * 64; idx += 256) {
        int j = idx >> 6, k = idx & 63;
        sW[k * 64 + j] = Wr[idx];
    }
    __syncthreads();

    // pass 2: acc += x @ Wr^T
    #pragma unroll 2
    for (int k = 0; k < 64; k += 4) {
        float4 a[8];
        #pragma unroll
        for (int r = 0; r < 8; r++)
            a[r] = *(const float4*)&sA[(i0 + r) * AP + k];
        #pragma unroll
        for (int kk = 0; kk < 4; kk++) {
            ulonglong2 wp = *(const ulonglong2*)&sW[(k + kk) * 64 + j0];
            #pragma unroll
            for (int r = 0; r < 8; r++) {
                float s = (kk == 0) ? a[r].x : (kk == 1) ? a[r].y
                        : (kk == 2) ? a[r].z : a[r].w;
                unsigned long long p = bcast2(s);
                fma2(accp[r][0], p, wp.x);
                fma2(accp[r][1], p, wp.y);
            }
        }
    }

    // unpack
    float acc[8][4];
    #pragma unroll
    for (int r = 0; r < 8; r++) {
        unpack2(accp[r][0], acc[r][0], acc[r][1]);
        unpack2(accp[r][1], acc[r][2], acc[r][3]);
    }

    if (mode == 0) {
        #pragma unroll
        for (int r = 0; r < 8; r++) {
            int node = node0 + i0 + r;
            if (node < n) {
                float4 st; float v;
                v = acc[r][0]; st.x = (v >= 0.f) ? v : 0.01f * v;
                v = acc[r][1]; st.y = (v >= 0.f) ? v : 0.01f * v;
                v = acc[r][2]; st.z = (v >= 0.f) ? v : 0.01f * v;
                v = acc[r][3]; st.w = (v >= 0.f) ? v : 0.01f * v;
                *(float4*)&out[(size_t)node * 64 + j0] = st;
            }
        }
    } else {
        // stage into sA, per-row L2 normalize
        __syncthreads();
        #pragma unroll
        for (int r = 0; r < 8; r++)
            *(float4*)&sA[(i0 + r) * AP + j0] =
                make_float4(acc[r][0], acc[r][1], acc[r][2], acc[r][3]);
        __syncthreads();
        #pragma unroll
        for (int it = 0; it < 16; it++) {
            int ni = wid + it * 8;
            int node = node0 + ni;
            if (node >= n) continue;
            float2 v = *(const float2*)&sA[ni * AP + 2 * lane];
            float ss = v.x * v.x + v.y * v.y;
            #pragma unroll
            for (int o = 16; o > 0; o >>= 1)
                ss += __shfl_xor_sync(0xffffffffu, ss, o);
            float s = 1.0f / fmaxf(sqrtf(ss), 1e-12f);
            *(float2*)&out[(size_t)node * 64 + 2 * lane] =
                make_float2(v.x * s, v.y * s);
        }
    }
}

// ================= launch (kernels ONLY — no host API calls) =================
extern "C" void kernel_launch(void* const* d_in, const int* in_sizes, int n_in,
                              void* d_out, int out_size)
{
    const float* x    = (const float*)d_in[0];
    const void*  edge = (const void*)d_in[1];
    // d_in[2] = edge_weight (ignored by SAGEConv)
    const float* W1l = (const float*)d_in[3];
    const float* b1  = (const float*)d_in[4];
    const float* W1r = (const float*)d_in[5];
    const float* W2l = (const float*)d_in[6];
    const float* b2  = (const float*)d_in[7];
    const float* W2r = (const float*)d_in[8];
    float* out = (float*)d_out;

    int n = in_sizes[0] / DD;
    int e = in_sizes[1] / 2;
    int nb = (n + SCAN_CHUNK - 1) / SCAN_CHUNK;

    detect_init_kernel<<<(n + 255) / 256, 256>>>(edge, n);
    convert_count_kernel<<<(e + 255) / 256, 256>>>(edge, e, n);
    bsum_kernel<<<nb, SCAN_CHUNK>>>(n);
    scan_kernel<<<nb, SCAN_CHUNK>>>(n, e);
    fill_kernel<<<(e + 255) / 256, 256>>>(e);

    int nblocks = (n + NPB - 1) / NPB;
    layer_kernel<<<nblocks, 256>>>(x, W1l, b1, W1r, nullptr, n, 0); // -> g_h1
    layer_kernel<<<nblocks, 256>>>(x, W2l, b2, W2r, out,     n, 1); // g_h1 -> out
}

// round 10
// speedup vs baseline: 1.2975x; 1.2975x over previous
#include <cuda_runtime.h>

#define NMAX 50000
#define EMAX 800000
#define DD 64
#define NPB 64            // dst nodes per block
#define AP 64             // sA pitch (row-major [node][k])
#define WP 68             // sW pitch (transposed [k][j])
#define SCAN_CHUNK 1024
#define MAXB ((NMAX + SCAN_CHUNK - 1) / SCAN_CHUNK)   // 49

// -------- device scratch (no allocations allowed) --------
__device__ int   g_is64;
__device__ int   g_src[EMAX];
__device__ int   g_dst[EMAX];
__device__ int   g_deg[NMAX];
__device__ int   g_rowptr[NMAX + 2];
__device__ int   g_cursor[NMAX];
__device__ int   g_col[EMAX];
__device__ int   g_bsum[MAXB + 1];
__device__ float g_h1[(size_t)NMAX * DD];

// ---- packed f32x2 helpers (sm_103a; ptxas never auto-emits FFMA2) ----
__device__ __forceinline__ unsigned long long bcast2(float a) {
    unsigned long long r;
    asm("mov.b64 %0, {%1, %1};" : "=l"(r) : "f"(a));
    return r;
}
__device__ __forceinline__ void fma2(unsigned long long& acc,
                                     unsigned long long a, unsigned long long b) {
    asm("fma.rn.f32x2 %0, %1, %2, %0;" : "+l"(acc) : "l"(a), "l"(b));
}
__device__ __forceinline__ void add2(unsigned long long& acc, unsigned long long b) {
    asm("add.rn.f32x2 %0, %0, %1;" : "+l"(acc) : "l"(b));
}
__device__ __forceinline__ void unpack2(unsigned long long p, float& lo, float& hi) {
    asm("mov.b64 {%0, %1}, %2;" : "=f"(lo), "=f"(hi) : "l"(p));
}

// ============ init deg + edge dtype detection (fused) ============
__global__ void detect_init_kernel(const void* __restrict__ edge, int n) {
    int i = blockIdx.x * blockDim.x + threadIdx.x;
    if (i < n) g_deg[i] = 0;
    if (i == 0) {
        const long long* p = (const long long*)edge;
        int ok = 1;
        for (int k = 0; k < 64; k++) {
            long long v = p[k];
            if (v < 0 || v >= n) { ok = 0; break; }
        }
        g_is64 = ok;
    }
}

// Materialize clamped int32 src/dst AND count degrees in one pass.
__global__ void convert_count_kernel(const void* __restrict__ edge, int e, int n) {
    int i = blockIdx.x * blockDim.x + threadIdx.x;
    if (i >= e) return;
    int s, d;
    if (g_is64) {
        const long long* p = (const long long*)edge;
        s = (int)p[i];
        d = (int)p[e + i];
    } else {
        const int* p = (const int*)edge;
        s = p[i];
        d = p[e + i];
    }
    s = min(max(s, 0), n - 1);
    d = min(max(d, 0), n - 1);
    g_src[i] = s;
    g_dst[i] = d;
    atomicAdd(&g_deg[d], 1);
}

// ============ coalesced scan: bsum -> scan (block offsets inlined) ============
__global__ void bsum_kernel(int n) {
    __shared__ int ws[32];
    int b = blockIdx.x, t = threadIdx.x;
    int lane = t & 31, wid = t >> 5;
    int i = b * SCAN_CHUNK + t;
    int v = (i < n) ? g_deg[i] : 0;
    #pragma unroll
    for (int o = 16; o > 0; o >>= 1) v += __shfl_xor_sync(0xffffffffu, v, o);
    if (lane == 0) ws[wid] = v;
    __syncthreads();
    if (t < 32) {
        int s = ws[t];
        #pragma unroll
        for (int o = 16; o > 0; o >>= 1) s += __shfl_xor_sync(0xffffffffu, s, o);
        if (t == 0) g_bsum[b] = s;
    }
}

// per-chunk exclusive scan; block offset computed in-kernel from g_bsum
__global__ void scan_kernel(int n, int e) {
    __shared__ int ws[32];
    __shared__ int sOff;
    int b = blockIdx.x, t = threadIdx.x;
    int lane = t & 31, wid = t >> 5;

    if (wid == 0) {
        int off = 0;
        for (int j = lane; j < b; j += 32) off += g_bsum[j];
        #pragma unroll
        for (int o = 16; o > 0; o >>= 1) off += __shfl_xor_sync(0xffffffffu, off, o);
        if (lane == 0) sOff = off;
    }

    int i = b * SCAN_CHUNK + t;
    int v = (i < n) ? g_deg[i] : 0;
    int x = v;
    #pragma unroll
    for (int o = 1; o < 32; o <<= 1) {
        int y = __shfl_up_sync(0xffffffffu, x, o);
        if (lane >= o) x += y;
    }
    if (lane == 31) ws[wid] = x;
    __syncthreads();
    if (wid == 0) {
        int w = ws[lane];
        #pragma unroll
        for (int o = 1; o < 32; o <<= 1) {
            int y = __shfl_up_sync(0xffffffffu, w, o);
            if (lane >= o) w += y;
        }
        ws[lane] = w;
    }
    __syncthreads();
    int incl = x + (wid > 0 ? ws[wid - 1] : 0);
    int excl = incl - v + sOff;
    if (i < n) { g_rowptr[i] = excl; g_cursor[i] = excl; }
    if (b == 0 && t == 0) g_rowptr[n] = e;
}

__global__ void fill_kernel(int e) {
    int i = blockIdx.x * blockDim.x + threadIdx.x;
    if (i < e) {
        int p = atomicAdd(&g_cursor[g_dst[i]], 1);
        g_col[p] = g_src[i];
    }
}

// ================= fused layer (round-8 winner, unchanged) =================
// mode 0: in = x param, out = g_h1, epilogue leaky_relu(0.01)
// mode 1: in = g_h1,    out = out param, epilogue row-L2-normalize
__global__ __launch_bounds__(256) void layer_kernel(
    const float* __restrict__ in_p,
    const float* __restrict__ Wl,      // [64,64] row-major
    const float* __restrict__ bias,    // [64]
    const float* __restrict__ Wr,      // [64,64] row-major
    float* __restrict__ out_p,
    int n, int mode)
{
    __shared__ float sA[NPB * AP];     // [64 nodes][64 k] row-major
    __shared__ float sW[64 * WP];      // [64 k][64 j] transposed weight
    __shared__ float sB[64];

    const float* __restrict__ in = (mode == 0) ? in_p : g_h1;
    float* __restrict__ out      = (mode == 0) ? g_h1 : out_p;

    int t = threadIdx.x;
    int wid = t >> 5, lane = t & 31;
    int half = lane >> 4;        // 0/1: which edge of the pair
    int c4 = (lane & 15) * 4;    // float4 column group
    int node0 = blockIdx.x * NPB;

    // load Wl^T and bias
    for (int idx = t; idx < 64 * 64; idx += 256) {
        int j = idx >> 6, k = idx & 63;
        sW[k * WP + j] = Wl[idx];
    }
    if (t < 64) sB[t] = bias[t];

    // ---- prefetch rowptr for this warp's 8 nodes (lanes 0..15) ----
    int pidx;
    if (lane < 8)       pidx = node0 + wid + lane * 8;
    else if (lane < 16) pidx = node0 + wid + (lane - 8) * 8 + 1;
    else                pidx = n;
    pidx = min(pidx, n);
    int rp = g_rowptr[pidx];

    // ---- prefetch self rows x[node] for all 8 nodes ----
    float2 xs[8];
    #pragma unroll
    for (int it = 0; it < 8; it++) {
        int node = min(node0 + wid + it * 8, n - 1);
        xs[it] = *(const float2*)&in[(size_t)node * 64 + 2 * lane];
    }

    // ---- phase 1: mean aggregation -> sA ----
    #pragma unroll
    for (int it = 0; it < 8; it++) {
        int ni = wid + it * 8;
        int node = node0 + ni;
        float4 a0 = {0.f, 0.f, 0.f, 0.f}, a1 = {0.f, 0.f, 0.f, 0.f};
        int beg = __shfl_sync(0xffffffffu, rp, it);
        int end = __shfl_sync(0xffffffffu, rp, it + 8);
        if (node < n) {
            int e0 = beg;
            for (; e0 + 4 <= end; e0 += 4) {
                int sa = g_col[e0 + half];
                int sb = g_col[e0 + 2 + half];
                float4 v0 = *(const float4*)&in[(size_t)sa * 64 + c4];
                float4 v1 = *(const float4*)&in[(size_t)sb * 64 + c4];
                a0.x += v0.x; a0.y += v0.y; a0.z += v0.z; a0.w += v0.w;
                a1.x += v1.x; a1.y += v1.y; a1.z += v1.z; a1.w += v1.w;
            }
            if (e0 + 2 <= end) {
                int sa = g_col[e0 + half];
                float4 v0 = *(const float4*)&in[(size_t)sa * 64 + c4];
                a0.x += v0.x; a0.y += v0.y; a0.z += v0.z; a0.w += v0.w;
                e0 += 2;
            }
            if (e0 < end && half == 0) {
                int sa = g_col[e0];
                float4 v0 = *(const float4*)&in[(size_t)sa * 64 + c4];
                a1.x += v0.x; a1.y += v0.y; a1.z += v0.z; a1.w += v0.w;
            }
            a0.x += a1.x; a0.y += a1.y; a0.z += a1.z; a0.w += a1.w;
            a0.x += __shfl_xor_sync(0xffffffffu, a0.x, 16);
            a0.y += __shfl_xor_sync(0xffffffffu, a0.y, 16);
            a0.z += __shfl_xor_sync(0xffffffffu, a0.z, 16);
            a0.w += __shfl_xor_sync(0xffffffffu, a0.w, 16);
            int deg = end - beg;
            float inv = 1.0f / (float)(deg > 0 ? deg : 1);
            a0.x *= inv; a0.y *= inv; a0.z *= inv; a0.w *= inv;
        }
        if (half == 0)
            *(float4*)&sA[ni * AP + c4] = a0;
    }
    __syncthreads();

    // ---- GEMM with packed f32x2 accumulators (4x4 tile) ----
    int rg = t >> 4, cg = t & 15;
    int i0 = rg * 4, j0 = cg * 4;
    unsigned long long accp[4][2] = {};

    // pass 1: acc += mean @ Wl^T
    #pragma unroll 4
    for (int k = 0; k < 64; k += 4) {
        float4 a0 = *(const float4*)&sA[(i0 + 0) * AP + k];
        float4 a1 = *(const float4*)&sA[(i0 + 1) * AP + k];
        float4 a2 = *(const float4*)&sA[(i0 + 2) * AP + k];
        float4 a3 = *(const float4*)&sA[(i0 + 3) * AP + k];
        #pragma unroll
        for (int kk = 0; kk < 4; kk++) {
            ulonglong2 wp = *(const ulonglong2*)&sW[(k + kk) * WP + j0];
            float s0 = (kk == 0) ? a0.x : (kk == 1) ? a0.y : (kk == 2) ? a0.z : a0.w;
            float s1 = (kk == 0) ? a1.x : (kk == 1) ? a1.y : (kk == 2) ? a1.z : a1.w;
            float s2 = (kk == 0) ? a2.x : (kk == 1) ? a2.y : (kk == 2) ? a2.z : a2.w;
            float s3 = (kk == 0) ? a3.x : (kk == 1) ? a3.y : (kk == 2) ? a3.z : a3.w;
            unsigned long long p;
            p = bcast2(s0); fma2(accp[0][0], p, wp.x); fma2(accp[0][1], p, wp.y);
            p = bcast2(s1); fma2(accp[1][0], p, wp.x); fma2(accp[1][1], p, wp.y);
            p = bcast2(s2); fma2(accp[2][0], p, wp.x); fma2(accp[2][1], p, wp.y);
            p = bcast2(s3); fma2(accp[3][0], p, wp.x); fma2(accp[3][1], p, wp.y);
        }
    }
    __syncthreads();

    // swap operands: sA <- x, sW <- Wr^T
    #pragma unroll
    for (int it = 0; it < 8; it++) {
        int ni = wid + it * 8;
        *(float2*)&sA[ni * AP + 2 * lane] = xs[it];
    }
    for (int idx = t; idx < 64 * 64; idx += 256) {
        int j = idx >> 6, k = idx & 63;
        sW[k * WP + j] = Wr[idx];
    }
    __syncthreads();

    // pass 2: acc += x @ Wr^T
    #pragma unroll 4
    for (int k = 0; k < 64; k += 4) {
        float4 a0 = *(const float4*)&sA[(i0 + 0) * AP + k];
        float4 a1 = *(const float4*)&sA[(i0 + 1) * AP + k];
        float4 a2 = *(const float4*)&sA[(i0 + 2) * AP + k];
        float4 a3 = *(const float4*)&sA[(i0 + 3) * AP + k];
        #pragma unroll
        for (int kk = 0; kk < 4; kk++) {
            ulonglong2 wp = *(const ulonglong2*)&sW[(k + kk) * WP + j0];
            float s0 = (kk == 0) ? a0.x : (kk == 1) ? a0.y : (kk == 2) ? a0.z : a0.w;
            float s1 = (kk == 0) ? a1.x : (kk == 1) ? a1.y : (kk == 2) ? a1.z : a1.w;
            float s2 = (kk == 0) ? a2.x : (kk == 1) ? a2.y : (kk == 2) ? a2.z : a2.w;
            float s3 = (kk == 0) ? a3.x : (kk == 1) ? a3.y : (kk == 2) ? a3.z : a3.w;
            unsigned long long p;
            p = bcast2(s0); fma2(accp[0][0], p, wp.x); fma2(accp[0][1], p, wp.y);
            p = bcast2(s1); fma2(accp[1][0], p, wp.x); fma2(accp[1][1], p, wp.y);
            p = bcast2(s2); fma2(accp[2][0], p, wp.x); fma2(accp[2][1], p, wp.y);
            p = bcast2(s3); fma2(accp[3][0], p, wp.x); fma2(accp[3][1], p, wp.y);
        }
    }

    // bias (packed) + unpack
    ulonglong2 bp = *(const ulonglong2*)&sB[j0];
    float acc[4][4];
    #pragma unroll
    for (int r = 0; r < 4; r++) {
        add2(accp[r][0], bp.x);
        add2(accp[r][1], bp.y);
        unpack2(accp[r][0], acc[r][0], acc[r][1]);
        unpack2(accp[r][1], acc[r][2], acc[r][3]);
    }

    if (mode == 0) {
        #pragma unroll
        for (int r = 0; r < 4; r++) {
            int node = node0 + i0 + r;
            if (node < n) {
                float4 st; float v;
                v = acc[r][0]; st.x = (v >= 0.f) ? v : 0.01f * v;
                v = acc[r][1]; st.y = (v >= 0.f) ? v : 0.01f * v;
                v = acc[r][2]; st.z = (v >= 0.f) ? v : 0.01f * v;
                v = acc[r][3]; st.w = (v >= 0.f) ? v : 0.01f * v;
                *(float4*)&out[(size_t)node * 64 + j0] = st;
            }
        }
    } else {
        // stage into sA, per-row L2 normalize
        __syncthreads();
        #pragma unroll
        for (int r = 0; r < 4; r++)
            *(float4*)&sA[(i0 + r) * AP + j0] =
                make_float4(acc[r][0], acc[r][1], acc[r][2], acc[r][3]);
        __syncthreads();
        #pragma unroll
        for (int it = 0; it < 8; it++) {
            int ni = wid + it * 8;
            int node = node0 + ni;
            if (node >= n) continue;
            float2 v = *(const float2*)&sA[ni * AP + 2 * lane];
            float ss = v.x * v.x + v.y * v.y;
            #pragma unroll
            for (int o = 16; o > 0; o >>= 1)
                ss += __shfl_xor_sync(0xffffffffu, ss, o);
            float s = 1.0f / fmaxf(sqrtf(ss), 1e-12f);
            *(float2*)&out[(size_t)node * 64 + 2 * lane] =
                make_float2(v.x * s, v.y * s);
        }
    }
}

// ================= launch (kernels ONLY — no host API calls) =================
extern "C" void kernel_launch(void* const* d_in, const int* in_sizes, int n_in,
                              void* d_out, int out_size)
{
    const float* x    = (const float*)d_in[0];
    const void*  edge = (const void*)d_in[1];
    // d_in[2] = edge_weight (ignored by SAGEConv)
    const float* W1l = (const float*)d_in[3];
    const float* b1  = (const float*)d_in[4];
    const float* W1r = (const float*)d_in[5];
    const float* W2l = (const float*)d_in[6];
    const float* b2  = (const float*)d_in[7];
    const float* W2r = (const float*)d_in[8];
    float* out = (float*)d_out;

    int n = in_sizes[0] / DD;
    int e = in_sizes[1] / 2;
    int nb = (n + SCAN_CHUNK - 1) / SCAN_CHUNK;

    detect_init_kernel<<<(n + 255) / 256, 256>>>(edge, n);
    convert_count_kernel<<<(e + 255) / 256, 256>>>(edge, e, n);
    bsum_kernel<<<nb, SCAN_CHUNK>>>(n);
    scan_kernel<<<nb, SCAN_CHUNK>>>(n, e);
    fill_kernel<<<(e + 255) / 256, 256>>>(e);

    int nblocks = (n + NPB - 1) / NPB;
    layer_kernel<<<nblocks, 256>>>(x, W1l, b1, W1r, nullptr, n, 0); // -> g_h1
    layer_kernel<<<nblocks, 256>>>(x, W2l, b2, W2r, out,     n, 1); // g_h1 -> out
}